// round 4
// baseline (speedup 1.0000x reference)
#include <cuda_runtime.h>

// Problem constants (from reference)
#define SEQ    4096
#define CIN    7
#define NK     586        // 585 regular kernels + 1 "last"
#define GLEN   12288      // SEQ * KW(3)
#define HP     12289      // output positions per channel-kernel row
#define GPITCH 12304      // GLEN + 16 (4 left pad + right slack), 16B-aligned rows
#define CTOT   4096       // 7*585 + 1
#define NQ     1024       // c-quads
#define HTILE  16

// Scratch (allocation-free rule: __device__ globals)
__device__ float g_Gpad[CIN * GPITCH];   // Gpad[ch][i] = g_ch[i-4] (0 outside)
__device__ float g_Wmid[NK * 8];         // middle column of each 8x3 kernel
__device__ ulonglong2 g_Wq[NQ * 8];      // per-quad packed weights: {(w_c0,w_c1),(w_c2,w_c3)} per tap

typedef unsigned long long u64;
__device__ __forceinline__ u64 pk2(float lo, float hi) {
    u64 r; asm("mov.b64 %0, {%1,%2};" : "=l"(r) : "f"(lo), "f"(hi)); return r;
}
__device__ __forceinline__ u64 fma2(u64 a, u64 b, u64 c) {
    u64 d; asm("fma.rn.f32x2 %0, %1, %2, %3;" : "=l"(d) : "l"(a), "l"(b), "l"(c)); return d;
}

// ---- fused prep: mid-column weights, per-quad packed weights, padded gathered signal ----
__global__ void prep(const float* __restrict__ x, const float* __restrict__ kernels) {
    int idx = blockIdx.x * blockDim.x + threadIdx.x;
    if (idx < NK * 8) {
        int k = idx >> 3, a = idx & 7;
        g_Wmid[idx] = kernels[k * 24 + a * 3 + 1];
    }
    if (idx < NQ * 8) {
        int q = idx >> 3, a = idx & 7;
        float w[4];
#pragma unroll
        for (int j = 0; j < 4; j++) {
            int c = 4 * q + j;
            int k = (c == CTOT - 1) ? 585 : (c % 585);
            w[j] = kernels[k * 24 + a * 3 + 1];
        }
        ulonglong2 v; v.x = pk2(w[0], w[1]); v.y = pk2(w[2], w[3]);
        g_Wq[idx] = v;
    }
    if (idx < CIN * GPITCH) {
        int ch = idx / GPITCH;
        int i  = idx - ch * GPITCH;
        int t  = i - 4;
        float v = 0.f;
        if (t >= 0 && t < GLEN) {
            int s = t / 3;
            int j = t - s * 3;
            int src = s + j;
            if (src > SEQ - 1) src = SEQ - 1;
            v = x[src * CIN + ch];
        }
        g_Gpad[idx] = v;
    }
}

// ---- main kernel: one c-quad per thread, HTILE rows, STG.128 per row ----
__global__ void __launch_bounds__(256, 4) conv_main(float* __restrict__ out) {
    const int tid = threadIdx.x;
    const int q   = blockIdx.x * 256 + tid;     // [0, 1024), grid.x = 4
    const int c0  = q * 4;
    const int h0  = blockIdx.y * HTILE;

    const int ch0 = c0 / 585;
    const int c3  = c0 + 3;
    const int ch3 = (c3 == CTOT - 1) ? 0 : c3 / 585;

    const bool uniform  = (ch0 == ch3);
    const bool fulltile = (h0 + HTILE <= HP);

    if (uniform && fulltile) {
        // 8 taps x 2 packed weight pairs per quad
        u64 W0[8], W1[8];
        {
            const ulonglong2* wq = &g_Wq[q * 8];
#pragma unroll
            for (int a = 0; a < 8; a++) { ulonglong2 t = wq[a]; W0[a] = t.x; W1[a] = t.y; }
        }

        const float* __restrict__ gp = &g_Gpad[ch0 * GPITCH + h0];

        // Window of 12 duplicated g values: P[i] = (g[hb+i], g[hb+i])
        u64 P[12];
        {
            float4 a0 = *(const float4*)(gp);
            float4 a1 = *(const float4*)(gp + 4);
            float4 a2 = *(const float4*)(gp + 8);
            P[0] = pk2(a0.x, a0.x); P[1]  = pk2(a0.y, a0.y);
            P[2] = pk2(a0.z, a0.z); P[3]  = pk2(a0.w, a0.w);
            P[4] = pk2(a1.x, a1.x); P[5]  = pk2(a1.y, a1.y);
            P[6] = pk2(a1.z, a1.z); P[7]  = pk2(a1.w, a1.w);
            P[8] = pk2(a2.x, a2.x); P[9]  = pk2(a2.y, a2.y);
            P[10] = pk2(a2.z, a2.z); P[11] = pk2(a2.w, a2.w);
        }

        char* op = (char*)(out + (size_t)h0 * CTOT + c0);
#pragma unroll
        for (int hb = 0; hb < HTILE; hb += 4) {
            float4 nxt;
            if (hb < HTILE - 4) nxt = *(const float4*)(gp + hb + 12);
#pragma unroll
            for (int u = 0; u < 4; u++) {
                u64 a0 = 0ull, a1 = 0ull;
#pragma unroll
                for (int a = 0; a < 8; a++) {
                    u64 g2 = P[u + a];
                    a0 = fma2(g2, W0[a], a0);
                    a1 = fma2(g2, W1[a], a1);
                }
                ulonglong2 st; st.x = a0; st.y = a1;
                *(ulonglong2*)op = st;              // STG.128: out[h][c0..c0+3]
                op += CTOT * sizeof(float);
            }
            if (hb < HTILE - 4) {
#pragma unroll
                for (int i = 0; i < 8; i++) P[i] = P[i + 4];
                P[8]  = pk2(nxt.x, nxt.x); P[9]  = pk2(nxt.y, nxt.y);
                P[10] = pk2(nxt.z, nxt.z); P[11] = pk2(nxt.w, nxt.w);
            }
        }
    } else {
        // Slow path: channel-crossing quads (7 of 1024) and the 1-row tail tile.
        int hEnd = min(h0 + HTILE, HP);
        int chv[4], kkv[4];
#pragma unroll
        for (int j = 0; j < 4; j++) {
            int c = c0 + j;
            if (c == CTOT - 1) { chv[j] = 0; kkv[j] = 585; }
            else               { chv[j] = c / 585; kkv[j] = c % 585; }
        }
        for (int h = h0; h < hEnd; h++) {
            float acc[4];
#pragma unroll
            for (int j = 0; j < 4; j++) {
                const float* gpj = &g_Gpad[chv[j] * GPITCH + h];
                float s = 0.f;
#pragma unroll
                for (int a = 0; a < 8; a++) s = fmaf(gpj[a], g_Wmid[kkv[j] * 8 + a], s);
                acc[j] = s;
            }
            float4 o; o.x = acc[0]; o.y = acc[1]; o.z = acc[2]; o.w = acc[3];
            *(float4*)&out[(size_t)h * CTOT + c0] = o;
        }
    }
}

extern "C" void kernel_launch(void* const* d_in, const int* in_sizes, int n_in,
                              void* d_out, int out_size) {
    const float* x       = (const float*)d_in[0];
    const float* kernels = (const float*)d_in[1];
    if (n_in >= 2 && in_sizes[0] == NK * 24) {   // defensive: swapped order
        kernels = (const float*)d_in[0];
        x       = (const float*)d_in[1];
    }
    float* out = (float*)d_out;

    prep<<<(CIN * GPITCH + 255) / 256, 256>>>(x, kernels);

    dim3 grid(NQ / 256, (HP + HTILE - 1) / HTILE);  // (4, 769)
    conv_main<<<grid, 256>>>(out);
}

// round 5
// speedup vs baseline: 1.0095x; 1.0095x over previous
#include <cuda_runtime.h>

// Problem constants (from reference)
#define SEQ    4096
#define CIN    7
#define NK     586        // 585 regular kernels + 1 "last"
#define GLEN   12288      // SEQ * KW(3)
#define HP     12289      // output positions per channel-kernel row
#define GPITCH 12304      // GLEN + 16 (4 left pad + right slack), 16B-aligned rows
#define CTOT   4096       // 7*585 + 1
#define NQ     1024       // c-quads
#define HTILE  16

// Scratch (allocation-free rule: __device__ globals)
__device__ float g_Gpad[CIN * GPITCH];   // Gpad[ch][i] = g_ch[i-4] (0 outside)
__device__ float g_Wmid[NK * 8];         // middle column of each 8x3 kernel
__device__ ulonglong2 g_Wq[NQ * 8];      // per-quad packed weights: {(w_c0,w_c1),(w_c2,w_c3)} per tap

typedef unsigned long long u64;
__device__ __forceinline__ u64 pk2(float lo, float hi) {
    u64 r; asm("mov.b64 %0, {%1,%2};" : "=l"(r) : "f"(lo), "f"(hi)); return r;
}
__device__ __forceinline__ u64 fma2(u64 a, u64 b, u64 c) {
    u64 d; asm("fma.rn.f32x2 %0, %1, %2, %3;" : "=l"(d) : "l"(a), "l"(b), "l"(c)); return d;
}

// ---- fused prep: mid-column weights, per-quad packed weights, padded gathered signal ----
__global__ void prep(const float* __restrict__ x, const float* __restrict__ kernels) {
    int idx = blockIdx.x * blockDim.x + threadIdx.x;
    if (idx < NK * 8) {
        int k = idx >> 3, a = idx & 7;
        g_Wmid[idx] = kernels[k * 24 + a * 3 + 1];
    }
    if (idx < NQ * 8) {
        int q = idx >> 3, a = idx & 7;
        float w[4];
#pragma unroll
        for (int j = 0; j < 4; j++) {
            int c = 4 * q + j;
            int k = (c == CTOT - 1) ? 585 : (c % 585);
            w[j] = kernels[k * 24 + a * 3 + 1];
        }
        ulonglong2 v; v.x = pk2(w[0], w[1]); v.y = pk2(w[2], w[3]);
        g_Wq[idx] = v;
    }
    if (idx < CIN * GPITCH) {
        int ch = idx / GPITCH;
        int i  = idx - ch * GPITCH;
        int t  = i - 4;
        float v = 0.f;
        if (t >= 0 && t < GLEN) {
            int s = t / 3;
            int j = t - s * 3;
            int src = s + j;
            if (src > SEQ - 1) src = SEQ - 1;
            v = x[src * CIN + ch];
        }
        g_Gpad[idx] = v;
    }
}

// ---- main kernel: one c-quad per thread, HTILE rows, STG.128 per row,
//      plain-float window with on-the-fly (g,g) packing to stay under 64 regs ----
__global__ void __launch_bounds__(256, 4) conv_main(float* __restrict__ out) {
    const int tid = threadIdx.x;
    const int q   = blockIdx.x * 256 + tid;     // [0, 1024), grid.x = 4
    const int c0  = q * 4;
    const int h0  = blockIdx.y * HTILE;

    const int ch0 = c0 / 585;
    const int c3  = c0 + 3;
    const int ch3 = (c3 == CTOT - 1) ? 0 : c3 / 585;

    const bool uniform  = (ch0 == ch3);
    const bool fulltile = (h0 + HTILE <= HP);

    if (uniform && fulltile) {
        // 8 taps x 2 packed weight pairs per quad (32 regs)
        u64 W0[8], W1[8];
        {
            const ulonglong2* wq = &g_Wq[q * 8];
#pragma unroll
            for (int a = 0; a < 8; a++) { ulonglong2 t = wq[a]; W0[a] = t.x; W1[a] = t.y; }
        }

        const float* __restrict__ gp = &g_Gpad[ch0 * GPITCH + h0];

        // Plain-float sliding window (12 regs)
        float r[12];
        {
            float4 a0 = *(const float4*)(gp);
            float4 a1 = *(const float4*)(gp + 4);
            float4 a2 = *(const float4*)(gp + 8);
            r[0]=a0.x; r[1]=a0.y; r[2]=a0.z;  r[3]=a0.w;
            r[4]=a1.x; r[5]=a1.y; r[6]=a1.z;  r[7]=a1.w;
            r[8]=a2.x; r[9]=a2.y; r[10]=a2.z; r[11]=a2.w;
        }

        char* op = (char*)(out + (size_t)h0 * CTOT + c0);
#pragma unroll
        for (int hb = 0; hb < HTILE; hb += 4) {
            float4 nxt;
            if (hb < HTILE - 4) nxt = *(const float4*)(gp + hb + 12);
#pragma unroll
            for (int u = 0; u < 4; u++) {
                u64 a0 = 0ull, a1 = 0ull;
#pragma unroll
                for (int a = 0; a < 8; a++) {
                    u64 g2 = pk2(r[u + a], r[u + a]);   // one MOV, reused twice
                    a0 = fma2(g2, W0[a], a0);
                    a1 = fma2(g2, W1[a], a1);
                }
                ulonglong2 st; st.x = a0; st.y = a1;
                *(ulonglong2*)op = st;                  // STG.128: out[h][c0..c0+3]
                op += CTOT * sizeof(float);
            }
            if (hb < HTILE - 4) {
#pragma unroll
                for (int i = 0; i < 8; i++) r[i] = r[i + 4];
                r[8] = nxt.x; r[9] = nxt.y; r[10] = nxt.z; r[11] = nxt.w;
            }
        }
    } else {
        // Slow path: channel-crossing quads (7 of 1024) and the 1-row tail tile.
        int hEnd = min(h0 + HTILE, HP);
        int chv[4], kkv[4];
#pragma unroll
        for (int j = 0; j < 4; j++) {
            int c = c0 + j;
            if (c == CTOT - 1) { chv[j] = 0; kkv[j] = 585; }
            else               { chv[j] = c / 585; kkv[j] = c % 585; }
        }
        for (int h = h0; h < hEnd; h++) {
            float acc[4];
#pragma unroll
            for (int j = 0; j < 4; j++) {
                const float* gpj = &g_Gpad[chv[j] * GPITCH + h];
                float s = 0.f;
#pragma unroll
                for (int a = 0; a < 8; a++) s = fmaf(gpj[a], g_Wmid[kkv[j] * 8 + a], s);
                acc[j] = s;
            }
            float4 o; o.x = acc[0]; o.y = acc[1]; o.z = acc[2]; o.w = acc[3];
            *(float4*)&out[(size_t)h * CTOT + c0] = o;
        }
    }
}

extern "C" void kernel_launch(void* const* d_in, const int* in_sizes, int n_in,
                              void* d_out, int out_size) {
    const float* x       = (const float*)d_in[0];
    const float* kernels = (const float*)d_in[1];
    if (n_in >= 2 && in_sizes[0] == NK * 24) {   // defensive: swapped order
        kernels = (const float*)d_in[0];
        x       = (const float*)d_in[1];
    }
    float* out = (float*)d_out;

    prep<<<(CIN * GPITCH + 255) / 256, 256>>>(x, kernels);

    dim3 grid(NQ / 256, (HP + HTILE - 1) / HTILE);  // (4, 769)
    conv_main<<<grid, 256>>>(out);
}